// round 15
// baseline (speedup 1.0000x reference)
#include <cuda_runtime.h>
#include <cuda_bf16.h>
#include <math.h>
#include <stdint.h>

// ---------------- problem constants ----------------
#define BATCH 2
#define TLEN  1024
#define DMODEL 1024
#define NHEAD 16
#define HDIM 64
#define NLAYER 6
#define VOCAB 32000
#define DFF 4096
#define NROWS (BATCH*TLEN)   // 2048
#define NQKV 3072

// ---------------- scratch (device globals) ----------------
__device__ float g_x[NROWS*DMODEL];
__device__ __nv_bfloat16 g_hhi[NROWS*DMODEL],   g_hlo[NROWS*DMODEL];
__device__ __nv_bfloat16 g_qkvhi[NROWS*NQKV],   g_qkvlo[NROWS*NQKV];
__device__ __nv_bfloat16 g_atthi[NROWS*DMODEL], g_attlo[NROWS*DMODEL];
__device__ __nv_bfloat16 g_ffhi[NROWS*DFF],     g_fflo[NROWS*DFF];

// weights arena (bf16 hi/lo, [K,N] layout; per-layer interleaved layout)
#define M1E 1048576ull
#define M4E 4194304ull
#define MQKVE (3ull*M1E)
#define LAYER_ELEMS (2ull*(MQKVE + M1E + 2ull*M4E))   // 24*M1E
#define WARENA_ELEMS (6ull*LAYER_ELEMS + 2ull*32768000ull)
__device__ __nv_bfloat16 g_wbuf[WARENA_ELEMS];

extern __shared__ __align__(1024) char g_smem[];

// ================= PTX helpers =================
__device__ __forceinline__ uint32_t smem_u32(const void* p) {
    uint32_t a;
    asm("{ .reg .u64 t; cvta.to.shared.u64 t, %1; cvt.u32.u64 %0, t; }" : "=r"(a) : "l"(p));
    return a;
}
__device__ __forceinline__ void cp_async16(uint32_t sm, const void* g) {
    asm volatile("cp.async.cg.shared.global [%0], [%1], 16;" :: "r"(sm), "l"(g) : "memory");
}
#define CP_COMMIT() asm volatile("cp.async.commit_group;" ::: "memory")
#define CP_WAIT1()  asm volatile("cp.async.wait_group 1;" ::: "memory")
#define CP_WAIT0()  asm volatile("cp.async.wait_group 0;" ::: "memory")

__device__ __forceinline__ void ldsm4(uint32_t* r, uint32_t addr) {
    asm volatile("ldmatrix.sync.aligned.m8n8.x4.shared.b16 {%0,%1,%2,%3}, [%4];"
        : "=r"(r[0]), "=r"(r[1]), "=r"(r[2]), "=r"(r[3]) : "r"(addr));
}
__device__ __forceinline__ void ldsm4t(uint32_t* r, uint32_t addr) {
    asm volatile("ldmatrix.sync.aligned.m8n8.x4.trans.shared.b16 {%0,%1,%2,%3}, [%4];"
        : "=r"(r[0]), "=r"(r[1]), "=r"(r[2]), "=r"(r[3]) : "r"(addr));
}
__device__ __forceinline__ void mma_bf16(float* c, const uint32_t* a, const uint32_t* b) {
    asm volatile(
        "mma.sync.aligned.m16n8k16.row.col.f32.bf16.bf16.f32 "
        "{%0,%1,%2,%3}, {%4,%5,%6,%7}, {%8,%9}, {%0,%1,%2,%3};"
        : "+f"(c[0]), "+f"(c[1]), "+f"(c[2]), "+f"(c[3])
        : "r"(a[0]), "r"(a[1]), "r"(a[2]), "r"(a[3]), "r"(b[0]), "r"(b[1]));
}

#define SW128(off) ((off) ^ (((off) >> 3) & 0x70))

// ---------------- splits (round-to-nearest) ----------------
__device__ __forceinline__ void split_bf16(float x, __nv_bfloat16& h, __nv_bfloat16& l)
{
    h = __float2bfloat16(x);
    l = __float2bfloat16(x - __bfloat162float(h));
}
__device__ __forceinline__ void split2pack(float x, float y, uint32_t& hi, uint32_t& lo)
{
    __nv_bfloat16 hx, lx, hy, ly;
    split_bf16(x, hx, lx); split_bf16(y, hy, ly);
    __nv_bfloat162 hv(hx, hy), lv(lx, ly);
    hi = *(uint32_t*)&hv;
    lo = *(uint32_t*)&lv;
}
__device__ __forceinline__ void split8pack(const float4 v0, const float4 v1,
                                           uint4& hi4, uint4& lo4)
{
    split2pack(v0.x, v0.y, hi4.x, lo4.x);
    split2pack(v0.z, v0.w, hi4.y, lo4.y);
    split2pack(v1.x, v1.y, hi4.z, lo4.z);
    split2pack(v1.z, v1.w, hi4.w, lo4.w);
}

// ---------------- embed ----------------
__global__ __launch_bounds__(256) void embed_kernel(
    const int* __restrict__ idx, const float* __restrict__ tok,
    const float* __restrict__ pos, float* __restrict__ x)
{
    int i = blockIdx.x * blockDim.x + threadIdx.x;
    int row = i >> 8;
    int c4  = (i & 255) * 4;
    int t = row & (TLEN - 1);
    int token = idx[row];
    float4 a = *(const float4*)(tok + (size_t)token * DMODEL + c4);
    float4 p = *(const float4*)(pos + (size_t)t * DMODEL + c4);
    float4 o; o.x = a.x + p.x; o.y = a.y + p.y; o.z = a.z + p.z; o.w = a.w + p.w;
    *(float4*)(x + (size_t)row * DMODEL + c4) = o;
}

// ---------------- layernorm (one-pass) -> bf16 hi/lo ----------------
__global__ __launch_bounds__(256) void ln_split_kernel(
    const float* __restrict__ x, const float* __restrict__ g,
    const float* __restrict__ b, __nv_bfloat16* __restrict__ hi,
    __nv_bfloat16* __restrict__ lo)
{
    __shared__ float2 sbuf[8];
    size_t row = blockIdx.x;
    const float* xr = x + row * DMODEL;
    int c = threadIdx.x * 4;
    float4 d = *(const float4*)(xr + c);
    float s1 = d.x + d.y + d.z + d.w;
    float s2 = d.x*d.x + d.y*d.y + d.z*d.z + d.w*d.w;
    #pragma unroll
    for (int o = 16; o; o >>= 1) {
        s1 += __shfl_xor_sync(0xffffffffu, s1, o);
        s2 += __shfl_xor_sync(0xffffffffu, s2, o);
    }
    int w = threadIdx.x >> 5;
    if ((threadIdx.x & 31) == 0) sbuf[w] = make_float2(s1, s2);
    __syncthreads();
    if (threadIdx.x < 32) {
        float2 r = (threadIdx.x < 8) ? sbuf[threadIdx.x] : make_float2(0.f, 0.f);
        #pragma unroll
        for (int o = 4; o; o >>= 1) {
            r.x += __shfl_xor_sync(0xffffffffu, r.x, o);
            r.y += __shfl_xor_sync(0xffffffffu, r.y, o);
        }
        if (threadIdx.x == 0) sbuf[0] = r;
    }
    __syncthreads();
    float mean = sbuf[0].x * (1.f / DMODEL);
    float var  = sbuf[0].y * (1.f / DMODEL) - mean * mean;
    float inv = rsqrtf(var + 1e-5f);
    float4 gg = *(const float4*)(g + c);
    float4 bb = *(const float4*)(b + c);
    float ox = (d.x - mean) * inv * gg.x + bb.x;
    float oy = (d.y - mean) * inv * gg.y + bb.y;
    float oz = (d.z - mean) * inv * gg.z + bb.z;
    float ow = (d.w - mean) * inv * gg.w + bb.w;
    uint32_t h0, l0, h1, l1;
    split2pack(ox, oy, h0, l0);
    split2pack(oz, ow, h1, l1);
    *(uint2*)(hi + row * DMODEL + c) = make_uint2(h0, h1);
    *(uint2*)(lo + row * DMODEL + c) = make_uint2(l0, l1);
}

// ---------------- batched weight split (all layers, one launch per tensor) --
__global__ __launch_bounds__(256) void convs_all_kernel(
    const float* __restrict__ W, __nv_bfloat16* __restrict__ hi0,
    __nv_bfloat16* __restrict__ lo0, int units_per_layer, size_t out_stride)
{
    int i = blockIdx.x * 256 + threadIdx.x;
    int l = i / units_per_layer;
    int r = i - l * units_per_layer;
    size_t in_off = ((size_t)l * units_per_layer + r) * 8;
    float4 v0 = *(const float4*)(W + in_off);
    float4 v1 = *(const float4*)(W + in_off + 4);
    uint4 h4, l4;
    split8pack(v0, v1, h4, l4);
    size_t oo = (size_t)l * out_stride + (size_t)r * 8;
    *(uint4*)(hi0 + oo) = h4;
    *(uint4*)(lo0 + oo) = l4;
}

// QKV gather+split, all layers
__global__ __launch_bounds__(256) void convqkv_all_kernel(
    const float* __restrict__ Wq, const float* __restrict__ Wk,
    const float* __restrict__ Wv, __nv_bfloat16* __restrict__ hi0,
    __nv_bfloat16* __restrict__ lo0)
{
    int i = blockIdx.x * 256 + threadIdx.x;
    const int upl = 1024 * (NQKV / 8);        // 393216
    int l = i / upl;
    int rem = i - l * upl;
    int k = rem / (NQKV / 8);
    int c8 = (rem % (NQKV / 8)) * 8;
    int which = c8 >> 10;
    int n = c8 & 1023;
    int head = n >> 6, e = n & 63;
    const float* W = ((which == 0) ? Wq : (which == 1) ? Wk : Wv) + (size_t)l * M1E;
    const float* src = W + (size_t)head * (DMODEL * HDIM) + (size_t)k * HDIM + e;
    float4 v0 = *(const float4*)(src);
    float4 v1 = *(const float4*)(src + 4);
    uint4 h4, l4;
    split8pack(v0, v1, h4, l4);
    size_t o = (size_t)l * LAYER_ELEMS + (size_t)k * NQKV + c8;
    *(uint4*)(hi0 + o) = h4;
    *(uint4*)(lo0 + o) = l4;
}

// ---------------- mma.sync GEMM (bf16x3), KC=64, single barrier/chunk ------
#define BM 128
#define BN 128
#define KC 64
#define NSTAGE 3
#define TILE_SZ 16384
#define STAGE_B (4*TILE_SZ)
#define GEMM_SMEM (NSTAGE*STAGE_B)   // 196608

__device__ __forceinline__ void load_tileA(
    const __nv_bfloat16* __restrict__ g, int K, int k0, uint32_t st, int tid)
{
    #pragma unroll
    for (int i = 0; i < 4; i++) {
        int idx = i * 256 + tid;
        int r = idx >> 3, u = idx & 7;
        const void* gp = (const char*)(g + (size_t)r * K + k0) + u * 16;
        cp_async16(st + SW128((uint32_t)(r * 128 + u * 16)), gp);
    }
}
__device__ __forceinline__ void load_tileB(
    const __nv_bfloat16* __restrict__ g, int N, int k0, int n0, uint32_t st, int tid)
{
    #pragma unroll
    for (int i = 0; i < 4; i++) {
        int idx = i * 256 + tid;
        int r = idx >> 4, u = idx & 15;
        const void* gp = (const char*)(g + (size_t)(k0 + r) * N + n0) + u * 16;
        uint32_t off = (uint32_t)(r * 256 + ((u * 16) ^ ((r & 7) << 4)));
        cp_async16(st + off, gp);
    }
}

template<bool BIAS, bool RELU, bool RES, bool SPLIT>
__global__ __launch_bounds__(256) void gemm_tc_kernel(
    const __nv_bfloat16* __restrict__ Ahi, const __nv_bfloat16* __restrict__ Alo,
    const __nv_bfloat16* __restrict__ Bhi, const __nv_bfloat16* __restrict__ Blo,
    const float* __restrict__ bias, const float* __restrict__ res,
    float* __restrict__ C, __nv_bfloat16* __restrict__ Chi,
    __nv_bfloat16* __restrict__ Clo, int N, int K)
{
    uint32_t sbase = smem_u32(g_smem);
    int tid = threadIdx.x, lane = tid & 31, wid = tid >> 5;
    int n0 = blockIdx.x * BN, m0 = blockIdx.y * BM;
    int wm = (wid & 1) * 64, wn = (wid >> 1) * 32;
    int NC = K / KC;

    const __nv_bfloat16* a_hi = Ahi + (size_t)m0 * K;
    const __nv_bfloat16* a_lo = Alo + (size_t)m0 * K;

    float acc[4][4][4];
    #pragma unroll
    for (int i = 0; i < 4; i++)
        #pragma unroll
        for (int j = 0; j < 4; j++)
            #pragma unroll
            for (int r = 0; r < 4; r++) acc[i][j][r] = 0.f;

    #pragma unroll
    for (int s = 0; s < 2; s++) {
        uint32_t st = sbase + s * STAGE_B;
        load_tileA(a_hi, K, s * KC, st,               tid);
        load_tileA(a_lo, K, s * KC, st + TILE_SZ,     tid);
        load_tileB(Bhi, N, s * KC, n0, st + 2*TILE_SZ, tid);
        load_tileB(Blo, N, s * KC, n0, st + 3*TILE_SZ, tid);
        CP_COMMIT();
    }

    int aq = lane >> 4;
    int arow_l = lane & 15;
    uint32_t a_sw = (uint32_t)((arow_l & 7) << 4);
    int bq = lane >> 3;
    int brow_l = lane & 7;

    for (int c = 0; c < NC; c++) {
        if (c < NC - 1) { CP_WAIT1(); } else { CP_WAIT0(); }
        __syncthreads();
        int nc = c + 2;
        if (nc < NC) {
            uint32_t stw = sbase + (uint32_t)(nc % NSTAGE) * STAGE_B;
            load_tileA(a_hi, K, nc * KC, stw,               tid);
            load_tileA(a_lo, K, nc * KC, stw + TILE_SZ,     tid);
            load_tileB(Bhi, N, nc * KC, n0, stw + 2*TILE_SZ, tid);
            load_tileB(Blo, N, nc * KC, n0, stw + 3*TILE_SZ, tid);
        }
        CP_COMMIT();

        uint32_t st = sbase + (uint32_t)(c % NSTAGE) * STAGE_B;
        uint32_t stA_hi = st, stA_lo = st + TILE_SZ;
        uint32_t stB_hi = st + 2 * TILE_SZ, stB_lo = st + 3 * TILE_SZ;

        #pragma unroll
        for (int ks = 0; ks < 4; ks++) {
            uint32_t a_colb = (uint32_t)(ks * 32 + aq * 16);
            uint32_t ahi_f[4][4], alo_f[4][4], bhi_f[4][2], blo_f[4][2];
            #pragma unroll
            for (int mt = 0; mt < 4; mt++) {
                uint32_t ro = (uint32_t)((wm + mt * 16 + arow_l) * 128);
                ldsm4(ahi_f[mt], stA_hi + ro + (a_colb ^ a_sw));
                ldsm4(alo_f[mt], stA_lo + ro + (a_colb ^ a_sw));
            }
            #pragma unroll
            for (int np = 0; np < 2; np++) {
                uint32_t srow = (uint32_t)(ks * 16 + (bq & 1) * 8 + brow_l);
                uint32_t cb = (uint32_t)(wn * 2 + np * 32 + (bq >> 1) * 16);
                uint32_t ad = srow * 256 + (cb ^ (uint32_t)(brow_l << 4));
                uint32_t r4[4];
                ldsm4t(r4, stB_hi + ad);
                bhi_f[np*2][0] = r4[0]; bhi_f[np*2][1] = r4[1];
                bhi_f[np*2+1][0] = r4[2]; bhi_f[np*2+1][1] = r4[3];
                ldsm4t(r4, stB_lo + ad);
                blo_f[np*2][0] = r4[0]; blo_f[np*2][1] = r4[1];
                blo_f[np*2+1][0] = r4[2]; blo_f[np*2+1][1] = r4[3];
            }
            #pragma unroll
            for (int mt = 0; mt < 4; mt++)
                #pragma unroll
                for (int nt = 0; nt < 4; nt++) {
                    mma_bf16(acc[mt][nt], ahi_f[mt], bhi_f[nt]);
                    mma_bf16(acc[mt][nt], ahi_f[mt], blo_f[nt]);
                    mma_bf16(acc[mt][nt], alo_f[mt], bhi_f[nt]);
                }
        }
    }

    int mrow = lane >> 2, ncol = (lane & 3) * 2;
    #pragma unroll
    for (int mt = 0; mt < 4; mt++) {
        #pragma unroll
        for (int nt = 0; nt < 4; nt++) {
            size_t m = (size_t)(m0 + wm + mt * 16 + mrow);
            int n = n0 + wn + nt * 8 + ncol;
            float2 v0 = make_float2(acc[mt][nt][0], acc[mt][nt][1]);
            float2 v1 = make_float2(acc[mt][nt][2], acc[mt][nt][3]);
            if (BIAS) {
                float2 bb = *(const float2*)(bias + n);
                v0.x += bb.x; v0.y += bb.y; v1.x += bb.x; v1.y += bb.y;
            }
            if (RES) {
                float2 r0 = *(const float2*)(res + m * N + n);
                float2 r1 = *(const float2*)(res + (m + 8) * N + n);
                v0.x += r0.x; v0.y += r0.y; v1.x += r1.x; v1.y += r1.y;
            }
            if (RELU) {
                v0.x = fmaxf(v0.x, 0.f); v0.y = fmaxf(v0.y, 0.f);
                v1.x = fmaxf(v1.x, 0.f); v1.y = fmaxf(v1.y, 0.f);
            }
            if (SPLIT) {
                uint32_t hh, ll;
                split2pack(v0.x, v0.y, hh, ll);
                *(uint32_t*)(Chi + m * N + n) = hh;
                *(uint32_t*)(Clo + m * N + n) = ll;
                split2pack(v1.x, v1.y, hh, ll);
                *(uint32_t*)(Chi + (m + 8) * N + n) = hh;
                *(uint32_t*)(Clo + (m + 8) * N + n) = ll;
            } else {
                *(float2*)(C + m * N + n) = v0;
                *(float2*)(C + (m + 8) * N + n) = v1;
            }
        }
    }
}

// ---------------- tensor-core flash attention (bf16x3, KV double-buffered) --
#define ATT_SMEM (16384 + 2*32768)   // 81920

__global__ __launch_bounds__(128) void attn_tc_kernel(
    const __nv_bfloat16* __restrict__ Qhi, const __nv_bfloat16* __restrict__ Qlo,
    const __nv_bfloat16* __restrict__ Khi, const __nv_bfloat16* __restrict__ Klo,
    const __nv_bfloat16* __restrict__ Vhi, const __nv_bfloat16* __restrict__ Vlo,
    __nv_bfloat16* __restrict__ Ohi, __nv_bfloat16* __restrict__ Olo, int qstr)
{
    uint32_t sb = smem_u32(g_smem);
    uint32_t sQh = sb, sQl = sb + 8192;
    int qt = (int)gridDim.x - 1 - (int)blockIdx.x;   // heaviest q-tiles first
    int h = blockIdx.y, b = blockIdx.z;
    int tid = threadIdx.x, lane = tid & 31, w = tid >> 5;
    size_t rowbase = (size_t)b * TLEN;
    int cofs = h * HDIM;

    {
        const __nv_bfloat16* qh = Qhi + (rowbase + qt * 64) * qstr + cofs;
        const __nv_bfloat16* ql = Qlo + (rowbase + qt * 64) * qstr + cofs;
        #pragma unroll
        for (int i = 0; i < 4; i++) {
            int idx = i * 128 + tid;
            int r = idx >> 3, u = idx & 7;
            uint32_t off = SW128((uint32_t)(r * 128 + u * 16));
            cp_async16(sQh + off, qh + (size_t)r * qstr + u * 8);
            cp_async16(sQl + off, ql + (size_t)r * qstr + u * 8);
        }
        CP_COMMIT();
    }
    {
        uint32_t stg = sb + 16384;
        const __nv_bfloat16* kh = Khi + rowbase * qstr + cofs;
        const __nv_bfloat16* kl = Klo + rowbase * qstr + cofs;
        const __nv_bfloat16* vh = Vhi + rowbase * qstr + cofs;
        const __nv_bfloat16* vl = Vlo + rowbase * qstr + cofs;
        #pragma unroll
        for (int i = 0; i < 4; i++) {
            int idx = i * 128 + tid;
            int r = idx >> 3, u = idx & 7;
            uint32_t off = SW128((uint32_t)(r * 128 + u * 16));
            size_t go = (size_t)r * qstr + u * 8;
            cp_async16(stg + off,          kh + go);
            cp_async16(stg + 8192 + off,   kl + go);
            cp_async16(stg + 16384 + off,  vh + go);
            cp_async16(stg + 24576 + off,  vl + go);
        }
        CP_COMMIT();
    }

    float m0r = -1e30f, m1r = -1e30f, l0r = 0.f, l1r = 0.f;
    float o[8][4];
    #pragma unroll
    for (int e = 0; e < 8; e++)
        #pragma unroll
        for (int r = 0; r < 4; r++) o[e][r] = 0.f;

    int g = lane >> 2;
    int c2 = (lane & 3) * 2;
    uint32_t a_sw = (uint32_t)((lane & 7) << 4);
    int aq = lane >> 4, arow_l = lane & 15;
    int bq = lane >> 3, brow_l = lane & 7;
    int b_rowloc = (bq >> 1) * 8 + brow_l;
    uint32_t b_colsel = (uint32_t)((bq & 1) * 16);

    for (int jt = 0; jt <= qt; jt++) {
        CP_WAIT0();
        __syncthreads();
        if (jt + 1 <= qt) {
            uint32_t stg = sb + 16384 + (uint32_t)((jt + 1) & 1) * 32768;
            const __nv_bfloat16* kh = Khi + (rowbase + (jt+1) * 64) * qstr + cofs;
            const __nv_bfloat16* kl = Klo + (rowbase + (jt+1) * 64) * qstr + cofs;
            const __nv_bfloat16* vh = Vhi + (rowbase + (jt+1) * 64) * qstr + cofs;
            const __nv_bfloat16* vl = Vlo + (rowbase + (jt+1) * 64) * qstr + cofs;
            #pragma unroll
            for (int i = 0; i < 4; i++) {
                int idx = i * 128 + tid;
                int r = idx >> 3, u = idx & 7;
                uint32_t off = SW128((uint32_t)(r * 128 + u * 16));
                size_t go = (size_t)r * qstr + u * 8;
                cp_async16(stg + off,          kh + go);
                cp_async16(stg + 8192 + off,   kl + go);
                cp_async16(stg + 16384 + off,  vh + go);
                cp_async16(stg + 24576 + off,  vl + go);
            }
        }
        CP_COMMIT();

        uint32_t stg = sb + 16384 + (uint32_t)(jt & 1) * 32768;
        uint32_t sKh = stg, sKl = stg + 8192, sVh = stg + 16384, sVl = stg + 24576;

        float s[8][4];
        #pragma unroll
        for (int nt = 0; nt < 8; nt++)
            #pragma unroll
            for (int r = 0; r < 4; r++) s[nt][r] = 0.f;

        #pragma unroll
        for (int ks = 0; ks < 4; ks++) {
            uint32_t qh_f[4], ql_f[4];
            uint32_t ro = (uint32_t)((w * 16 + arow_l) * 128);
            uint32_t cb = (uint32_t)(ks * 32 + aq * 16);
            ldsm4(qh_f, sQh + ro + (cb ^ a_sw));
            ldsm4(ql_f, sQl + ro + (cb ^ a_sw));
            #pragma unroll
            for (int np = 0; np < 4; np++) {
                uint32_t rk = (uint32_t)((np * 16 + b_rowloc) * 128);
                uint32_t cbk = (uint32_t)(ks * 32) + b_colsel;
                uint32_t swk = (uint32_t)(brow_l << 4);
                uint32_t kh4[4], kl4[4];
                ldsm4(kh4, sKh + rk + (cbk ^ swk));
                ldsm4(kl4, sKl + rk + (cbk ^ swk));
                uint32_t bh0[2] = {kh4[0], kh4[1]}, bh1[2] = {kh4[2], kh4[3]};
                uint32_t bl0[2] = {kl4[0], kl4[1]}, bl1[2] = {kl4[2], kl4[3]};
                mma_bf16(s[2*np],   qh_f, bh0);
                mma_bf16(s[2*np],   qh_f, bl0);
                mma_bf16(s[2*np],   ql_f, bh0);
                mma_bf16(s[2*np+1], qh_f, bh1);
                mma_bf16(s[2*np+1], qh_f, bl1);
                mma_bf16(s[2*np+1], ql_f, bh1);
            }
        }

        const float scale = 0.125f;
        #pragma unroll
        for (int nt = 0; nt < 8; nt++)
            #pragma unroll
            for (int r = 0; r < 4; r++) s[nt][r] *= scale;
        if (jt == qt) {
            int row0 = w * 16 + g, row1 = row0 + 8;
            #pragma unroll
            for (int nt = 0; nt < 8; nt++) {
                int cc = nt * 8 + c2;
                if (cc     > row0) s[nt][0] = -1e30f;
                if (cc + 1 > row0) s[nt][1] = -1e30f;
                if (cc     > row1) s[nt][2] = -1e30f;
                if (cc + 1 > row1) s[nt][3] = -1e30f;
            }
        }

        float mx0 = -1e30f, mx1 = -1e30f;
        #pragma unroll
        for (int nt = 0; nt < 8; nt++) {
            mx0 = fmaxf(mx0, fmaxf(s[nt][0], s[nt][1]));
            mx1 = fmaxf(mx1, fmaxf(s[nt][2], s[nt][3]));
        }
        mx0 = fmaxf(mx0, __shfl_xor_sync(0xffffffffu, mx0, 1));
        mx0 = fmaxf(mx0, __shfl_xor_sync(0xffffffffu, mx0, 2));
        mx1 = fmaxf(mx1, __shfl_xor_sync(0xffffffffu, mx1, 1));
        mx1 = fmaxf(mx1, __shfl_xor_sync(0xffffffffu, mx1, 2));
        float mn0 = fmaxf(m0r, mx0), mn1 = fmaxf(m1r, mx1);
        float al0 = __expf(m0r - mn0), al1 = __expf(m1r - mn1);
        float sm0 = 0.f, sm1 = 0.f;
        #pragma unroll
        for (int nt = 0; nt < 8; nt++) {
            s[nt][0] = __expf(s[nt][0] - mn0);
            s[nt][1] = __expf(s[nt][1] - mn0);
            s[nt][2] = __expf(s[nt][2] - mn1);
            s[nt][3] = __expf(s[nt][3] - mn1);
            sm0 += s[nt][0] + s[nt][1];
            sm1 += s[nt][2] + s[nt][3];
        }
        sm0 += __shfl_xor_sync(0xffffffffu, sm0, 1);
        sm0 += __shfl_xor_sync(0xffffffffu, sm0, 2);
        sm1 += __shfl_xor_sync(0xffffffffu, sm1, 1);
        sm1 += __shfl_xor_sync(0xffffffffu, sm1, 2);
        l0r = l0r * al0 + sm0;
        l1r = l1r * al1 + sm1;
        m0r = mn0; m1r = mn1;
        #pragma unroll
        for (int e = 0; e < 8; e++) {
            o[e][0] *= al0; o[e][1] *= al0;
            o[e][2] *= al1; o[e][3] *= al1;
        }

        #pragma unroll
        for (int ks = 0; ks < 4; ks++) {
            uint32_t pa_h[4], pa_l[4];
            split2pack(s[2*ks][0],   s[2*ks][1],   pa_h[0], pa_l[0]);
            split2pack(s[2*ks][2],   s[2*ks][3],   pa_h[1], pa_l[1]);
            split2pack(s[2*ks+1][0], s[2*ks+1][1], pa_h[2], pa_l[2]);
            split2pack(s[2*ks+1][2], s[2*ks+1][3], pa_h[3], pa_l[3]);
            #pragma unroll
            for (int np = 0; np < 4; np++) {
                uint32_t srow = (uint32_t)(ks * 16 + (bq & 1) * 8 + brow_l);
                uint32_t cbv = (uint32_t)(np * 32 + (bq >> 1) * 16);
                uint32_t swv = (uint32_t)(brow_l << 4);
                uint32_t vh4[4], vl4[4];
                ldsm4t(vh4, sVh + srow * 128 + (cbv ^ swv));
                ldsm4t(vl4, sVl + srow * 128 + (cbv ^ swv));
                uint32_t bh0[2] = {vh4[0], vh4[1]}, bh1[2] = {vh4[2], vh4[3]};
                uint32_t bl0[2] = {vl4[0], vl4[1]}, bl1[2] = {vl4[2], vl4[3]};
                mma_bf16(o[2*np],   pa_h, bh0);
                mma_bf16(o[2*np],   pa_h, bl0);
                mma_bf16(o[2*np],   pa_l, bh0);
                mma_bf16(o[2*np+1], pa_h, bh1);
                mma_bf16(o[2*np+1], pa_h, bl1);
                mma_bf16(o[2*np+1], pa_l, bh1);
            }
        }
    }

    float inv0 = 1.f / l0r, inv1 = 1.f / l1r;
    size_t r0 = rowbase + qt * 64 + w * 16 + g;
    size_t r1 = r0 + 8;
    #pragma unroll
    for (int e = 0; e < 8; e++) {
        int n = cofs + e * 8 + c2;
        uint32_t hh, ll;
        split2pack(o[e][0] * inv0, o[e][1] * inv0, hh, ll);
        *(uint32_t*)(Ohi + r0 * DMODEL + n) = hh;
        *(uint32_t*)(Olo + r0 * DMODEL + n) = ll;
        split2pack(o[e][2] * inv1, o[e][3] * inv1, hh, ll);
        *(uint32_t*)(Ohi + r1 * DMODEL + n) = hh;
        *(uint32_t*)(Olo + r1 * DMODEL + n) = ll;
    }
}

// ---------------- launcher ----------------
extern "C" void kernel_launch(void* const* d_in, const int* in_sizes, int n_in,
                              void* d_out, int out_size)
{
    const int*   idx  = (const int*)d_in[0];
    const float* tok  = (const float*)d_in[1];
    const float* pos  = (const float*)d_in[2];
    const float* Wq   = (const float*)d_in[3];
    const float* Wk   = (const float*)d_in[4];
    const float* Wv   = (const float*)d_in[5];
    const float* Wo   = (const float*)d_in[6];
    const float* bo   = (const float*)d_in[7];
    const float* ln1g = (const float*)d_in[8];
    const float* ln1b = (const float*)d_in[9];
    const float* ln2g = (const float*)d_in[10];
    const float* ln2b = (const float*)d_in[11];
    const float* W1   = (const float*)d_in[12];
    const float* b1   = (const float*)d_in[13];
    const float* W2   = (const float*)d_in[14];
    const float* b2   = (const float*)d_in[15];
    const float* lnfg = (const float*)d_in[16];
    const float* lnfb = (const float*)d_in[17];
    const float* Wh   = (const float*)d_in[18];
    const float* bh   = (const float*)d_in[19];
    float* out = (float*)d_out;

    float* x;
    __nv_bfloat16 *hhi,*hlo,*qkvhi,*qkvlo,*athi,*atlo,*ffhi,*fflo,*wbuf;
    cudaGetSymbolAddress((void**)&x, g_x);
    cudaGetSymbolAddress((void**)&hhi, g_hhi);    cudaGetSymbolAddress((void**)&hlo, g_hlo);
    cudaGetSymbolAddress((void**)&qkvhi, g_qkvhi);cudaGetSymbolAddress((void**)&qkvlo, g_qkvlo);
    cudaGetSymbolAddress((void**)&athi, g_atthi); cudaGetSymbolAddress((void**)&atlo, g_attlo);
    cudaGetSymbolAddress((void**)&ffhi, g_ffhi);  cudaGetSymbolAddress((void**)&fflo, g_fflo);
    cudaGetSymbolAddress((void**)&wbuf, g_wbuf);

    cudaFuncSetAttribute(attn_tc_kernel, cudaFuncAttributeMaxDynamicSharedMemorySize, ATT_SMEM);
    cudaFuncSetAttribute(gemm_tc_kernel<false,false,false,true>, cudaFuncAttributeMaxDynamicSharedMemorySize, GEMM_SMEM);
    cudaFuncSetAttribute(gemm_tc_kernel<true,true,false,true>,   cudaFuncAttributeMaxDynamicSharedMemorySize, GEMM_SMEM);
    cudaFuncSetAttribute(gemm_tc_kernel<true,false,true,false>,  cudaFuncAttributeMaxDynamicSharedMemorySize, GEMM_SMEM);
    cudaFuncSetAttribute(gemm_tc_kernel<true,false,false,false>, cudaFuncAttributeMaxDynamicSharedMemorySize, GEMM_SMEM);

    // ---- weight conversion: 5 launches, per-layer arena layout ----
    const size_t M1 = M1E, M4 = M4E, MQKV = MQKVE;
    __nv_bfloat16* wh_hi = wbuf + 6 * LAYER_ELEMS;
    __nv_bfloat16* wh_lo = wh_hi + (size_t)VOCAB * DMODEL;

    convqkv_all_kernel<<<9216, 256>>>(Wq, Wk, Wv, wbuf, wbuf + MQKV);
    convs_all_kernel<<<3072, 256>>>(Wo, wbuf + 2*MQKV, wbuf + 2*MQKV + M1,
                                    (int)(M1/8), LAYER_ELEMS);
    convs_all_kernel<<<12288, 256>>>(W1, wbuf + 2*MQKV + 2*M1, wbuf + 2*MQKV + 2*M1 + M4,
                                     (int)(M4/8), LAYER_ELEMS);
    convs_all_kernel<<<12288, 256>>>(W2, wbuf + 2*MQKV + 2*M1 + 2*M4,
                                     wbuf + 2*MQKV + 2*M1 + 3*M4,
                                     (int)(M4/8), LAYER_ELEMS);
    convs_all_kernel<<<16000, 256>>>(Wh, wh_hi, wh_lo, (int)(32768000ull/8), 0);

    // ---- forward ----
    embed_kernel<<<NROWS, 256>>>(idx, tok, pos, x);

    dim3 gQKV(NQKV/BN, NROWS/BM);
    dim3 gD(DMODEL/BN, NROWS/BM);
    dim3 gF(DFF/BN, NROWS/BM);
    dim3 gV(VOCAB/BN, NROWS/BM);

    for (int l = 0; l < NLAYER; l++) {
        __nv_bfloat16* base = wbuf + (size_t)l * LAYER_ELEMS;
        __nv_bfloat16* qkv_hi = base;                 __nv_bfloat16* qkv_lo = base + MQKV;
        __nv_bfloat16* wo_hi  = base + 2*MQKV;        __nv_bfloat16* wo_lo  = wo_hi + M1;
        __nv_bfloat16* w1_hi  = wo_hi + 2*M1;         __nv_bfloat16* w1_lo  = w1_hi + M4;
        __nv_bfloat16* w2_hi  = w1_hi + 2*M4;         __nv_bfloat16* w2_lo  = w2_hi + M4;

        ln_split_kernel<<<NROWS, 256>>>(x, ln1g + l*DMODEL, ln1b + l*DMODEL, hhi, hlo);
        gemm_tc_kernel<false,false,false,true><<<gQKV, 256, GEMM_SMEM>>>(
            hhi, hlo, qkv_hi, qkv_lo, nullptr, nullptr, nullptr, qkvhi, qkvlo, NQKV, DMODEL);

        attn_tc_kernel<<<dim3(TLEN/64, NHEAD, BATCH), 128, ATT_SMEM>>>(
            qkvhi, qkvlo, qkvhi + 1024, qkvlo + 1024, qkvhi + 2048, qkvlo + 2048,
            athi, atlo, NQKV);

        gemm_tc_kernel<true,false,true,false><<<gD, 256, GEMM_SMEM>>>(
            athi, atlo, wo_hi, wo_lo, bo + l*DMODEL, x, x, nullptr, nullptr, DMODEL, DMODEL);

        ln_split_kernel<<<NROWS, 256>>>(x, ln2g + l*DMODEL, ln2b + l*DMODEL, hhi, hlo);
        gemm_tc_kernel<true,true,false,true><<<gF, 256, GEMM_SMEM>>>(
            hhi, hlo, w1_hi, w1_lo, b1 + (size_t)l*DFF, nullptr, nullptr, ffhi, fflo, DFF, DMODEL);

        gemm_tc_kernel<true,false,true,false><<<gD, 256, GEMM_SMEM>>>(
            ffhi, fflo, w2_hi, w2_lo, b2 + l*DMODEL, x, x, nullptr, nullptr, DMODEL, DFF);
    }

    ln_split_kernel<<<NROWS, 256>>>(x, lnfg, lnfb, hhi, hlo);
    gemm_tc_kernel<true,false,false,false><<<gV, 256, GEMM_SMEM>>>(
        hhi, hlo, wh_hi, wh_lo, bh, nullptr, out, nullptr, nullptr, VOCAB, DMODEL);
}

// round 16
// speedup vs baseline: 1.0033x; 1.0033x over previous
#include <cuda_runtime.h>
#include <cuda_bf16.h>
#include <math.h>
#include <stdint.h>

// ---------------- problem constants ----------------
#define BATCH 2
#define TLEN  1024
#define DMODEL 1024
#define NHEAD 16
#define HDIM 64
#define NLAYER 6
#define VOCAB 32000
#define DFF 4096
#define NROWS (BATCH*TLEN)   // 2048
#define NQKV 3072

// ---------------- scratch (device globals) ----------------
__device__ float g_x[NROWS*DMODEL];
__device__ __nv_bfloat16 g_hhi[NROWS*DMODEL],   g_hlo[NROWS*DMODEL];
__device__ __nv_bfloat16 g_qkvhi[NROWS*NQKV],   g_qkvlo[NROWS*NQKV];
__device__ __nv_bfloat16 g_atthi[NROWS*DMODEL], g_attlo[NROWS*DMODEL];
__device__ __nv_bfloat16 g_ffhi[NROWS*DFF],     g_fflo[NROWS*DFF];

// weights arena (bf16 hi/lo, [K,N] layout; per-layer interleaved layout)
#define M1E 1048576ull
#define M4E 4194304ull
#define MQKVE (3ull*M1E)
#define LAYER_ELEMS (2ull*(MQKVE + M1E + 2ull*M4E))   // 24*M1E
#define WARENA_ELEMS (6ull*LAYER_ELEMS + 2ull*32768000ull)
__device__ __nv_bfloat16 g_wbuf[WARENA_ELEMS];

extern __shared__ __align__(1024) char g_smem[];

// ================= PTX helpers =================
__device__ __forceinline__ uint32_t smem_u32(const void* p) {
    uint32_t a;
    asm("{ .reg .u64 t; cvta.to.shared.u64 t, %1; cvt.u32.u64 %0, t; }" : "=r"(a) : "l"(p));
    return a;
}
__device__ __forceinline__ void cp_async16(uint32_t sm, const void* g) {
    asm volatile("cp.async.cg.shared.global [%0], [%1], 16;" :: "r"(sm), "l"(g) : "memory");
}
#define CP_COMMIT() asm volatile("cp.async.commit_group;" ::: "memory")
#define CP_WAIT1()  asm volatile("cp.async.wait_group 1;" ::: "memory")
#define CP_WAIT0()  asm volatile("cp.async.wait_group 0;" ::: "memory")

__device__ __forceinline__ void ldsm4(uint32_t* r, uint32_t addr) {
    asm volatile("ldmatrix.sync.aligned.m8n8.x4.shared.b16 {%0,%1,%2,%3}, [%4];"
        : "=r"(r[0]), "=r"(r[1]), "=r"(r[2]), "=r"(r[3]) : "r"(addr));
}
__device__ __forceinline__ void ldsm4t(uint32_t* r, uint32_t addr) {
    asm volatile("ldmatrix.sync.aligned.m8n8.x4.trans.shared.b16 {%0,%1,%2,%3}, [%4];"
        : "=r"(r[0]), "=r"(r[1]), "=r"(r[2]), "=r"(r[3]) : "r"(addr));
}
__device__ __forceinline__ void mma_bf16(float* c, const uint32_t* a, const uint32_t* b) {
    asm volatile(
        "mma.sync.aligned.m16n8k16.row.col.f32.bf16.bf16.f32 "
        "{%0,%1,%2,%3}, {%4,%5,%6,%7}, {%8,%9}, {%0,%1,%2,%3};"
        : "+f"(c[0]), "+f"(c[1]), "+f"(c[2]), "+f"(c[3])
        : "r"(a[0]), "r"(a[1]), "r"(a[2]), "r"(a[3]), "r"(b[0]), "r"(b[1]));
}

#define SW128(off) ((off) ^ (((off) >> 3) & 0x70))

// ---------------- splits (round-to-nearest) ----------------
__device__ __forceinline__ void split_bf16(float x, __nv_bfloat16& h, __nv_bfloat16& l)
{
    h = __float2bfloat16(x);
    l = __float2bfloat16(x - __bfloat162float(h));
}
__device__ __forceinline__ void split2pack(float x, float y, uint32_t& hi, uint32_t& lo)
{
    __nv_bfloat16 hx, lx, hy, ly;
    split_bf16(x, hx, lx); split_bf16(y, hy, ly);
    __nv_bfloat162 hv(hx, hy), lv(lx, ly);
    hi = *(uint32_t*)&hv;
    lo = *(uint32_t*)&lv;
}
__device__ __forceinline__ void split8pack(const float4 v0, const float4 v1,
                                           uint4& hi4, uint4& lo4)
{
    split2pack(v0.x, v0.y, hi4.x, lo4.x);
    split2pack(v0.z, v0.w, hi4.y, lo4.y);
    split2pack(v1.x, v1.y, hi4.z, lo4.z);
    split2pack(v1.z, v1.w, hi4.w, lo4.w);
}

// ---------------- embed ----------------
__global__ __launch_bounds__(256) void embed_kernel(
    const int* __restrict__ idx, const float* __restrict__ tok,
    const float* __restrict__ pos, float* __restrict__ x)
{
    int i = blockIdx.x * blockDim.x + threadIdx.x;
    int row = i >> 8;
    int c4  = (i & 255) * 4;
    int t = row & (TLEN - 1);
    int token = idx[row];
    float4 a = *(const float4*)(tok + (size_t)token * DMODEL + c4);
    float4 p = *(const float4*)(pos + (size_t)t * DMODEL + c4);
    float4 o; o.x = a.x + p.x; o.y = a.y + p.y; o.z = a.z + p.z; o.w = a.w + p.w;
    *(float4*)(x + (size_t)row * DMODEL + c4) = o;
}

// ---------------- layernorm: 2 rows/block, 1 barrier, 8 elems/thread ------
__global__ __launch_bounds__(256) void ln_split_kernel(
    const float* __restrict__ x, const float* __restrict__ g,
    const float* __restrict__ b, __nv_bfloat16* __restrict__ hi,
    __nv_bfloat16* __restrict__ lo)
{
    __shared__ float2 sbuf[2][4];
    int tid = threadIdx.x;
    int half = tid >> 7;            // 0 or 1: which row of the pair
    int t = tid & 127;
    size_t row = (size_t)blockIdx.x * 2 + half;
    int c = t * 8;
    const float* xr = x + row * DMODEL;
    float4 d0 = *(const float4*)(xr + c);
    float4 d1 = *(const float4*)(xr + c + 4);
    float s1 = d0.x + d0.y + d0.z + d0.w + d1.x + d1.y + d1.z + d1.w;
    float s2 = d0.x*d0.x + d0.y*d0.y + d0.z*d0.z + d0.w*d0.w
             + d1.x*d1.x + d1.y*d1.y + d1.z*d1.z + d1.w*d1.w;
    #pragma unroll
    for (int o = 16; o; o >>= 1) {
        s1 += __shfl_xor_sync(0xffffffffu, s1, o);
        s2 += __shfl_xor_sync(0xffffffffu, s2, o);
    }
    int w = t >> 5;                 // warp within half: 0..3
    if ((t & 31) == 0) sbuf[half][w] = make_float2(s1, s2);
    __syncthreads();
    float2 tot = make_float2(
        sbuf[half][0].x + sbuf[half][1].x + sbuf[half][2].x + sbuf[half][3].x,
        sbuf[half][0].y + sbuf[half][1].y + sbuf[half][2].y + sbuf[half][3].y);
    float mean = tot.x * (1.f / DMODEL);
    float var  = tot.y * (1.f / DMODEL) - mean * mean;
    float inv = rsqrtf(var + 1e-5f);
    float4 g0 = *(const float4*)(g + c);
    float4 g1 = *(const float4*)(g + c + 4);
    float4 b0 = *(const float4*)(b + c);
    float4 b1 = *(const float4*)(b + c + 4);
    float4 o0, o1;
    o0.x = (d0.x - mean) * inv * g0.x + b0.x;
    o0.y = (d0.y - mean) * inv * g0.y + b0.y;
    o0.z = (d0.z - mean) * inv * g0.z + b0.z;
    o0.w = (d0.w - mean) * inv * g0.w + b0.w;
    o1.x = (d1.x - mean) * inv * g1.x + b1.x;
    o1.y = (d1.y - mean) * inv * g1.y + b1.y;
    o1.z = (d1.z - mean) * inv * g1.z + b1.z;
    o1.w = (d1.w - mean) * inv * g1.w + b1.w;
    uint4 h4, l4;
    split8pack(o0, o1, h4, l4);
    *(uint4*)(hi + row * DMODEL + c) = h4;
    *(uint4*)(lo + row * DMODEL + c) = l4;
}

// ---------------- batched weight split (all layers, one launch per tensor) --
__global__ __launch_bounds__(256) void convs_all_kernel(
    const float* __restrict__ W, __nv_bfloat16* __restrict__ hi0,
    __nv_bfloat16* __restrict__ lo0, int units_per_layer, size_t out_stride)
{
    int i = blockIdx.x * 256 + threadIdx.x;
    int l = i / units_per_layer;
    int r = i - l * units_per_layer;
    size_t in_off = ((size_t)l * units_per_layer + r) * 8;
    float4 v0 = *(const float4*)(W + in_off);
    float4 v1 = *(const float4*)(W + in_off + 4);
    uint4 h4, l4;
    split8pack(v0, v1, h4, l4);
    size_t oo = (size_t)l * out_stride + (size_t)r * 8;
    *(uint4*)(hi0 + oo) = h4;
    *(uint4*)(lo0 + oo) = l4;
}

// QKV gather+split, all layers
__global__ __launch_bounds__(256) void convqkv_all_kernel(
    const float* __restrict__ Wq, const float* __restrict__ Wk,
    const float* __restrict__ Wv, __nv_bfloat16* __restrict__ hi0,
    __nv_bfloat16* __restrict__ lo0)
{
    int i = blockIdx.x * 256 + threadIdx.x;
    const int upl = 1024 * (NQKV / 8);        // 393216
    int l = i / upl;
    int rem = i - l * upl;
    int k = rem / (NQKV / 8);
    int c8 = (rem % (NQKV / 8)) * 8;
    int which = c8 >> 10;
    int n = c8 & 1023;
    int head = n >> 6, e = n & 63;
    const float* W = ((which == 0) ? Wq : (which == 1) ? Wk : Wv) + (size_t)l * M1E;
    const float* src = W + (size_t)head * (DMODEL * HDIM) + (size_t)k * HDIM + e;
    float4 v0 = *(const float4*)(src);
    float4 v1 = *(const float4*)(src + 4);
    uint4 h4, l4;
    split8pack(v0, v1, h4, l4);
    size_t o = (size_t)l * LAYER_ELEMS + (size_t)k * NQKV + c8;
    *(uint4*)(hi0 + o) = h4;
    *(uint4*)(lo0 + o) = l4;
}

// ---------------- mma.sync GEMM (bf16x3), KC=64, single barrier/chunk ------
#define BM 128
#define BN 128
#define KC 64
#define NSTAGE 3
#define TILE_SZ 16384
#define STAGE_B (4*TILE_SZ)
#define GEMM_SMEM (NSTAGE*STAGE_B)   // 196608

__device__ __forceinline__ void load_tileA(
    const __nv_bfloat16* __restrict__ g, int K, int k0, uint32_t st, int tid)
{
    #pragma unroll
    for (int i = 0; i < 4; i++) {
        int idx = i * 256 + tid;
        int r = idx >> 3, u = idx & 7;
        const void* gp = (const char*)(g + (size_t)r * K + k0) + u * 16;
        cp_async16(st + SW128((uint32_t)(r * 128 + u * 16)), gp);
    }
}
__device__ __forceinline__ void load_tileB(
    const __nv_bfloat16* __restrict__ g, int N, int k0, int n0, uint32_t st, int tid)
{
    #pragma unroll
    for (int i = 0; i < 4; i++) {
        int idx = i * 256 + tid;
        int r = idx >> 4, u = idx & 15;
        const void* gp = (const char*)(g + (size_t)(k0 + r) * N + n0) + u * 16;
        uint32_t off = (uint32_t)(r * 256 + ((u * 16) ^ ((r & 7) << 4)));
        cp_async16(st + off, gp);
    }
}

template<bool BIAS, bool RELU, bool RES, bool SPLIT>
__global__ __launch_bounds__(256) void gemm_tc_kernel(
    const __nv_bfloat16* __restrict__ Ahi, const __nv_bfloat16* __restrict__ Alo,
    const __nv_bfloat16* __restrict__ Bhi, const __nv_bfloat16* __restrict__ Blo,
    const float* __restrict__ bias, const float* __restrict__ res,
    float* __restrict__ C, __nv_bfloat16* __restrict__ Chi,
    __nv_bfloat16* __restrict__ Clo, int N, int K)
{
    uint32_t sbase = smem_u32(g_smem);
    int tid = threadIdx.x, lane = tid & 31, wid = tid >> 5;
    int n0 = blockIdx.x * BN, m0 = blockIdx.y * BM;
    int wm = (wid & 1) * 64, wn = (wid >> 1) * 32;
    int NC = K / KC;

    const __nv_bfloat16* a_hi = Ahi + (size_t)m0 * K;
    const __nv_bfloat16* a_lo = Alo + (size_t)m0 * K;

    float acc[4][4][4];
    #pragma unroll
    for (int i = 0; i < 4; i++)
        #pragma unroll
        for (int j = 0; j < 4; j++)
            #pragma unroll
            for (int r = 0; r < 4; r++) acc[i][j][r] = 0.f;

    #pragma unroll
    for (int s = 0; s < 2; s++) {
        uint32_t st = sbase + s * STAGE_B;
        load_tileA(a_hi, K, s * KC, st,               tid);
        load_tileA(a_lo, K, s * KC, st + TILE_SZ,     tid);
        load_tileB(Bhi, N, s * KC, n0, st + 2*TILE_SZ, tid);
        load_tileB(Blo, N, s * KC, n0, st + 3*TILE_SZ, tid);
        CP_COMMIT();
    }

    int aq = lane >> 4;
    int arow_l = lane & 15;
    uint32_t a_sw = (uint32_t)((arow_l & 7) << 4);
    int bq = lane >> 3;
    int brow_l = lane & 7;

    for (int c = 0; c < NC; c++) {
        if (c < NC - 1) { CP_WAIT1(); } else { CP_WAIT0(); }
        __syncthreads();
        int nc = c + 2;
        if (nc < NC) {
            uint32_t stw = sbase + (uint32_t)(nc % NSTAGE) * STAGE_B;
            load_tileA(a_hi, K, nc * KC, stw,               tid);
            load_tileA(a_lo, K, nc * KC, stw + TILE_SZ,     tid);
            load_tileB(Bhi, N, nc * KC, n0, stw + 2*TILE_SZ, tid);
            load_tileB(Blo, N, nc * KC, n0, stw + 3*TILE_SZ, tid);
        }
        CP_COMMIT();

        uint32_t st = sbase + (uint32_t)(c % NSTAGE) * STAGE_B;
        uint32_t stA_hi = st, stA_lo = st + TILE_SZ;
        uint32_t stB_hi = st + 2 * TILE_SZ, stB_lo = st + 3 * TILE_SZ;

        #pragma unroll
        for (int ks = 0; ks < 4; ks++) {
            uint32_t a_colb = (uint32_t)(ks * 32 + aq * 16);
            uint32_t ahi_f[4][4], alo_f[4][4], bhi_f[4][2], blo_f[4][2];
            #pragma unroll
            for (int mt = 0; mt < 4; mt++) {
                uint32_t ro = (uint32_t)((wm + mt * 16 + arow_l) * 128);
                ldsm4(ahi_f[mt], stA_hi + ro + (a_colb ^ a_sw));
                ldsm4(alo_f[mt], stA_lo + ro + (a_colb ^ a_sw));
            }
            #pragma unroll
            for (int np = 0; np < 2; np++) {
                uint32_t srow = (uint32_t)(ks * 16 + (bq & 1) * 8 + brow_l);
                uint32_t cb = (uint32_t)(wn * 2 + np * 32 + (bq >> 1) * 16);
                uint32_t ad = srow * 256 + (cb ^ (uint32_t)(brow_l << 4));
                uint32_t r4[4];
                ldsm4t(r4, stB_hi + ad);
                bhi_f[np*2][0] = r4[0]; bhi_f[np*2][1] = r4[1];
                bhi_f[np*2+1][0] = r4[2]; bhi_f[np*2+1][1] = r4[3];
                ldsm4t(r4, stB_lo + ad);
                blo_f[np*2][0] = r4[0]; blo_f[np*2][1] = r4[1];
                blo_f[np*2+1][0] = r4[2]; blo_f[np*2+1][1] = r4[3];
            }
            #pragma unroll
            for (int mt = 0; mt < 4; mt++)
                #pragma unroll
                for (int nt = 0; nt < 4; nt++) {
                    mma_bf16(acc[mt][nt], ahi_f[mt], bhi_f[nt]);
                    mma_bf16(acc[mt][nt], ahi_f[mt], blo_f[nt]);
                    mma_bf16(acc[mt][nt], alo_f[mt], bhi_f[nt]);
                }
        }
    }

    int mrow = lane >> 2, ncol = (lane & 3) * 2;
    #pragma unroll
    for (int mt = 0; mt < 4; mt++) {
        #pragma unroll
        for (int nt = 0; nt < 4; nt++) {
            size_t m = (size_t)(m0 + wm + mt * 16 + mrow);
            int n = n0 + wn + nt * 8 + ncol;
            float2 v0 = make_float2(acc[mt][nt][0], acc[mt][nt][1]);
            float2 v1 = make_float2(acc[mt][nt][2], acc[mt][nt][3]);
            if (BIAS) {
                float2 bb = *(const float2*)(bias + n);
                v0.x += bb.x; v0.y += bb.y; v1.x += bb.x; v1.y += bb.y;
            }
            if (RES) {
                float2 r0 = *(const float2*)(res + m * N + n);
                float2 r1 = *(const float2*)(res + (m + 8) * N + n);
                v0.x += r0.x; v0.y += r0.y; v1.x += r1.x; v1.y += r1.y;
            }
            if (RELU) {
                v0.x = fmaxf(v0.x, 0.f); v0.y = fmaxf(v0.y, 0.f);
                v1.x = fmaxf(v1.x, 0.f); v1.y = fmaxf(v1.y, 0.f);
            }
            if (SPLIT) {
                uint32_t hh, ll;
                split2pack(v0.x, v0.y, hh, ll);
                *(uint32_t*)(Chi + m * N + n) = hh;
                *(uint32_t*)(Clo + m * N + n) = ll;
                split2pack(v1.x, v1.y, hh, ll);
                *(uint32_t*)(Chi + (m + 8) * N + n) = hh;
                *(uint32_t*)(Clo + (m + 8) * N + n) = ll;
            } else {
                *(float2*)(C + m * N + n) = v0;
                *(float2*)(C + (m + 8) * N + n) = v1;
            }
        }
    }
}

// ---------------- tensor-core flash attention (bf16x3, KV double-buffered) --
#define ATT_SMEM (16384 + 2*32768)   // 81920

__global__ __launch_bounds__(128) void attn_tc_kernel(
    const __nv_bfloat16* __restrict__ Qhi, const __nv_bfloat16* __restrict__ Qlo,
    const __nv_bfloat16* __restrict__ Khi, const __nv_bfloat16* __restrict__ Klo,
    const __nv_bfloat16* __restrict__ Vhi, const __nv_bfloat16* __restrict__ Vlo,
    __nv_bfloat16* __restrict__ Ohi, __nv_bfloat16* __restrict__ Olo, int qstr)
{
    uint32_t sb = smem_u32(g_smem);
    uint32_t sQh = sb, sQl = sb + 8192;
    int qt = blockIdx.x;
    int h = blockIdx.y, b = blockIdx.z;
    int tid = threadIdx.x, lane = tid & 31, w = tid >> 5;
    size_t rowbase = (size_t)b * TLEN;
    int cofs = h * HDIM;

    {
        const __nv_bfloat16* qh = Qhi + (rowbase + qt * 64) * qstr + cofs;
        const __nv_bfloat16* ql = Qlo + (rowbase + qt * 64) * qstr + cofs;
        #pragma unroll
        for (int i = 0; i < 4; i++) {
            int idx = i * 128 + tid;
            int r = idx >> 3, u = idx & 7;
            uint32_t off = SW128((uint32_t)(r * 128 + u * 16));
            cp_async16(sQh + off, qh + (size_t)r * qstr + u * 8);
            cp_async16(sQl + off, ql + (size_t)r * qstr + u * 8);
        }
        CP_COMMIT();
    }
    {
        uint32_t stg = sb + 16384;
        const __nv_bfloat16* kh = Khi + rowbase * qstr + cofs;
        const __nv_bfloat16* kl = Klo + rowbase * qstr + cofs;
        const __nv_bfloat16* vh = Vhi + rowbase * qstr + cofs;
        const __nv_bfloat16* vl = Vlo + rowbase * qstr + cofs;
        #pragma unroll
        for (int i = 0; i < 4; i++) {
            int idx = i * 128 + tid;
            int r = idx >> 3, u = idx & 7;
            uint32_t off = SW128((uint32_t)(r * 128 + u * 16));
            size_t go = (size_t)r * qstr + u * 8;
            cp_async16(stg + off,          kh + go);
            cp_async16(stg + 8192 + off,   kl + go);
            cp_async16(stg + 16384 + off,  vh + go);
            cp_async16(stg + 24576 + off,  vl + go);
        }
        CP_COMMIT();
    }

    float m0r = -1e30f, m1r = -1e30f, l0r = 0.f, l1r = 0.f;
    float o[8][4];
    #pragma unroll
    for (int e = 0; e < 8; e++)
        #pragma unroll
        for (int r = 0; r < 4; r++) o[e][r] = 0.f;

    int g = lane >> 2;
    int c2 = (lane & 3) * 2;
    uint32_t a_sw = (uint32_t)((lane & 7) << 4);
    int aq = lane >> 4, arow_l = lane & 15;
    int bq = lane >> 3, brow_l = lane & 7;
    int b_rowloc = (bq >> 1) * 8 + brow_l;
    uint32_t b_colsel = (uint32_t)((bq & 1) * 16);

    for (int jt = 0; jt <= qt; jt++) {
        CP_WAIT0();
        __syncthreads();
        if (jt + 1 <= qt) {
            uint32_t stg = sb + 16384 + (uint32_t)((jt + 1) & 1) * 32768;
            const __nv_bfloat16* kh = Khi + (rowbase + (jt+1) * 64) * qstr + cofs;
            const __nv_bfloat16* kl = Klo + (rowbase + (jt+1) * 64) * qstr + cofs;
            const __nv_bfloat16* vh = Vhi + (rowbase + (jt+1) * 64) * qstr + cofs;
            const __nv_bfloat16* vl = Vlo + (rowbase + (jt+1) * 64) * qstr + cofs;
            #pragma unroll
            for (int i = 0; i < 4; i++) {
                int idx = i * 128 + tid;
                int r = idx >> 3, u = idx & 7;
                uint32_t off = SW128((uint32_t)(r * 128 + u * 16));
                size_t go = (size_t)r * qstr + u * 8;
                cp_async16(stg + off,          kh + go);
                cp_async16(stg + 8192 + off,   kl + go);
                cp_async16(stg + 16384 + off,  vh + go);
                cp_async16(stg + 24576 + off,  vl + go);
            }
        }
        CP_COMMIT();

        uint32_t stg = sb + 16384 + (uint32_t)(jt & 1) * 32768;
        uint32_t sKh = stg, sKl = stg + 8192, sVh = stg + 16384, sVl = stg + 24576;

        float s[8][4];
        #pragma unroll
        for (int nt = 0; nt < 8; nt++)
            #pragma unroll
            for (int r = 0; r < 4; r++) s[nt][r] = 0.f;

        #pragma unroll
        for (int ks = 0; ks < 4; ks++) {
            uint32_t qh_f[4], ql_f[4];
            uint32_t ro = (uint32_t)((w * 16 + arow_l) * 128);
            uint32_t cb = (uint32_t)(ks * 32 + aq * 16);
            ldsm4(qh_f, sQh + ro + (cb ^ a_sw));
            ldsm4(ql_f, sQl + ro + (cb ^ a_sw));
            #pragma unroll
            for (int np = 0; np < 4; np++) {
                uint32_t rk = (uint32_t)((np * 16 + b_rowloc) * 128);
                uint32_t cbk = (uint32_t)(ks * 32) + b_colsel;
                uint32_t swk = (uint32_t)(brow_l << 4);
                uint32_t kh4[4], kl4[4];
                ldsm4(kh4, sKh + rk + (cbk ^ swk));
                ldsm4(kl4, sKl + rk + (cbk ^ swk));
                uint32_t bh0[2] = {kh4[0], kh4[1]}, bh1[2] = {kh4[2], kh4[3]};
                uint32_t bl0[2] = {kl4[0], kl4[1]}, bl1[2] = {kl4[2], kl4[3]};
                mma_bf16(s[2*np],   qh_f, bh0);
                mma_bf16(s[2*np],   qh_f, bl0);
                mma_bf16(s[2*np],   ql_f, bh0);
                mma_bf16(s[2*np+1], qh_f, bh1);
                mma_bf16(s[2*np+1], qh_f, bl1);
                mma_bf16(s[2*np+1], ql_f, bh1);
            }
        }

        const float scale = 0.125f;
        #pragma unroll
        for (int nt = 0; nt < 8; nt++)
            #pragma unroll
            for (int r = 0; r < 4; r++) s[nt][r] *= scale;
        if (jt == qt) {
            int row0 = w * 16 + g, row1 = row0 + 8;
            #pragma unroll
            for (int nt = 0; nt < 8; nt++) {
                int cc = nt * 8 + c2;
                if (cc     > row0) s[nt][0] = -1e30f;
                if (cc + 1 > row0) s[nt][1] = -1e30f;
                if (cc     > row1) s[nt][2] = -1e30f;
                if (cc + 1 > row1) s[nt][3] = -1e30f;
            }
        }

        float mx0 = -1e30f, mx1 = -1e30f;
        #pragma unroll
        for (int nt = 0; nt < 8; nt++) {
            mx0 = fmaxf(mx0, fmaxf(s[nt][0], s[nt][1]));
            mx1 = fmaxf(mx1, fmaxf(s[nt][2], s[nt][3]));
        }
        mx0 = fmaxf(mx0, __shfl_xor_sync(0xffffffffu, mx0, 1));
        mx0 = fmaxf(mx0, __shfl_xor_sync(0xffffffffu, mx0, 2));
        mx1 = fmaxf(mx1, __shfl_xor_sync(0xffffffffu, mx1, 1));
        mx1 = fmaxf(mx1, __shfl_xor_sync(0xffffffffu, mx1, 2));
        float mn0 = fmaxf(m0r, mx0), mn1 = fmaxf(m1r, mx1);
        float al0 = __expf(m0r - mn0), al1 = __expf(m1r - mn1);
        float sm0 = 0.f, sm1 = 0.f;
        #pragma unroll
        for (int nt = 0; nt < 8; nt++) {
            s[nt][0] = __expf(s[nt][0] - mn0);
            s[nt][1] = __expf(s[nt][1] - mn0);
            s[nt][2] = __expf(s[nt][2] - mn1);
            s[nt][3] = __expf(s[nt][3] - mn1);
            sm0 += s[nt][0] + s[nt][1];
            sm1 += s[nt][2] + s[nt][3];
        }
        sm0 += __shfl_xor_sync(0xffffffffu, sm0, 1);
        sm0 += __shfl_xor_sync(0xffffffffu, sm0, 2);
        sm1 += __shfl_xor_sync(0xffffffffu, sm1, 1);
        sm1 += __shfl_xor_sync(0xffffffffu, sm1, 2);
        l0r = l0r * al0 + sm0;
        l1r = l1r * al1 + sm1;
        m0r = mn0; m1r = mn1;
        #pragma unroll
        for (int e = 0; e < 8; e++) {
            o[e][0] *= al0; o[e][1] *= al0;
            o[e][2] *= al1; o[e][3] *= al1;
        }

        #pragma unroll
        for (int ks = 0; ks < 4; ks++) {
            uint32_t pa_h[4], pa_l[4];
            split2pack(s[2*ks][0],   s[2*ks][1],   pa_h[0], pa_l[0]);
            split2pack(s[2*ks][2],   s[2*ks][3],   pa_h[1], pa_l[1]);
            split2pack(s[2*ks+1][0], s[2*ks+1][1], pa_h[2], pa_l[2]);
            split2pack(s[2*ks+1][2], s[2*ks+1][3], pa_h[3], pa_l[3]);
            #pragma unroll
            for (int np = 0; np < 4; np++) {
                uint32_t srow = (uint32_t)(ks * 16 + (bq & 1) * 8 + brow_l);
                uint32_t cbv = (uint32_t)(np * 32 + (bq >> 1) * 16);
                uint32_t swv = (uint32_t)(brow_l << 4);
                uint32_t vh4[4], vl4[4];
                ldsm4t(vh4, sVh + srow * 128 + (cbv ^ swv));
                ldsm4t(vl4, sVl + srow * 128 + (cbv ^ swv));
                uint32_t bh0[2] = {vh4[0], vh4[1]}, bh1[2] = {vh4[2], vh4[3]};
                uint32_t bl0[2] = {vl4[0], vl4[1]}, bl1[2] = {vl4[2], vl4[3]};
                mma_bf16(o[2*np],   pa_h, bh0);
                mma_bf16(o[2*np],   pa_h, bl0);
                mma_bf16(o[2*np],   pa_l, bh0);
                mma_bf16(o[2*np+1], pa_h, bh1);
                mma_bf16(o[2*np+1], pa_h, bl1);
                mma_bf16(o[2*np+1], pa_l, bh1);
            }
        }
    }

    float inv0 = 1.f / l0r, inv1 = 1.f / l1r;
    size_t r0 = rowbase + qt * 64 + w * 16 + g;
    size_t r1 = r0 + 8;
    #pragma unroll
    for (int e = 0; e < 8; e++) {
        int n = cofs + e * 8 + c2;
        uint32_t hh, ll;
        split2pack(o[e][0] * inv0, o[e][1] * inv0, hh, ll);
        *(uint32_t*)(Ohi + r0 * DMODEL + n) = hh;
        *(uint32_t*)(Olo + r0 * DMODEL + n) = ll;
        split2pack(o[e][2] * inv1, o[e][3] * inv1, hh, ll);
        *(uint32_t*)(Ohi + r1 * DMODEL + n) = hh;
        *(uint32_t*)(Olo + r1 * DMODEL + n) = ll;
    }
}

// ---------------- launcher ----------------
extern "C" void kernel_launch(void* const* d_in, const int* in_sizes, int n_in,
                              void* d_out, int out_size)
{
    const int*   idx  = (const int*)d_in[0];
    const float* tok  = (const float*)d_in[1];
    const float* pos  = (const float*)d_in[2];
    const float* Wq   = (const float*)d_in[3];
    const float* Wk   = (const float*)d_in[4];
    const float* Wv   = (const float*)d_in[5];
    const float* Wo   = (const float*)d_in[6];
    const float* bo   = (const float*)d_in[7];
    const float* ln1g = (const float*)d_in[8];
    const float* ln1b = (const float*)d_in[9];
    const float* ln2g = (const float*)d_in[10];
    const float* ln2b = (const float*)d_in[11];
    const float* W1   = (const float*)d_in[12];
    const float* b1   = (const float*)d_in[13];
    const float* W2   = (const float*)d_in[14];
    const float* b2   = (const float*)d_in[15];
    const float* lnfg = (const float*)d_in[16];
    const float* lnfb = (const float*)d_in[17];
    const float* Wh   = (const float*)d_in[18];
    const float* bh   = (const float*)d_in[19];
    float* out = (float*)d_out;

    float* x;
    __nv_bfloat16 *hhi,*hlo,*qkvhi,*qkvlo,*athi,*atlo,*ffhi,*fflo,*wbuf;
    cudaGetSymbolAddress((void**)&x, g_x);
    cudaGetSymbolAddress((void**)&hhi, g_hhi);    cudaGetSymbolAddress((void**)&hlo, g_hlo);
    cudaGetSymbolAddress((void**)&qkvhi, g_qkvhi);cudaGetSymbolAddress((void**)&qkvlo, g_qkvlo);
    cudaGetSymbolAddress((void**)&athi, g_atthi); cudaGetSymbolAddress((void**)&atlo, g_attlo);
    cudaGetSymbolAddress((void**)&ffhi, g_ffhi);  cudaGetSymbolAddress((void**)&fflo, g_fflo);
    cudaGetSymbolAddress((void**)&wbuf, g_wbuf);

    cudaFuncSetAttribute(attn_tc_kernel, cudaFuncAttributeMaxDynamicSharedMemorySize, ATT_SMEM);
    cudaFuncSetAttribute(gemm_tc_kernel<false,false,false,true>, cudaFuncAttributeMaxDynamicSharedMemorySize, GEMM_SMEM);
    cudaFuncSetAttribute(gemm_tc_kernel<true,true,false,true>,   cudaFuncAttributeMaxDynamicSharedMemorySize, GEMM_SMEM);
    cudaFuncSetAttribute(gemm_tc_kernel<true,false,true,false>,  cudaFuncAttributeMaxDynamicSharedMemorySize, GEMM_SMEM);
    cudaFuncSetAttribute(gemm_tc_kernel<true,false,false,false>, cudaFuncAttributeMaxDynamicSharedMemorySize, GEMM_SMEM);

    // ---- weight conversion: 5 launches, per-layer arena layout ----
    const size_t M1 = M1E, M4 = M4E, MQKV = MQKVE;
    __nv_bfloat16* wh_hi = wbuf + 6 * LAYER_ELEMS;
    __nv_bfloat16* wh_lo = wh_hi + (size_t)VOCAB * DMODEL;

    convqkv_all_kernel<<<9216, 256>>>(Wq, Wk, Wv, wbuf, wbuf + MQKV);
    convs_all_kernel<<<3072, 256>>>(Wo, wbuf + 2*MQKV, wbuf + 2*MQKV + M1,
                                    (int)(M1/8), LAYER_ELEMS);
    convs_all_kernel<<<12288, 256>>>(W1, wbuf + 2*MQKV + 2*M1, wbuf + 2*MQKV + 2*M1 + M4,
                                     (int)(M4/8), LAYER_ELEMS);
    convs_all_kernel<<<12288, 256>>>(W2, wbuf + 2*MQKV + 2*M1 + 2*M4,
                                     wbuf + 2*MQKV + 2*M1 + 3*M4,
                                     (int)(M4/8), LAYER_ELEMS);
    convs_all_kernel<<<16000, 256>>>(Wh, wh_hi, wh_lo, (int)(32768000ull/8), 0);

    // ---- forward ----
    embed_kernel<<<NROWS, 256>>>(idx, tok, pos, x);

    dim3 gQKV(NQKV/BN, NROWS/BM);
    dim3 gD(DMODEL/BN, NROWS/BM);
    dim3 gF(DFF/BN, NROWS/BM);
    dim3 gV(VOCAB/BN, NROWS/BM);

    for (int l = 0; l < NLAYER; l++) {
        __nv_bfloat16* base = wbuf + (size_t)l * LAYER_ELEMS;
        __nv_bfloat16* qkv_hi = base;                 __nv_bfloat16* qkv_lo = base + MQKV;
        __nv_bfloat16* wo_hi  = base + 2*MQKV;        __nv_bfloat16* wo_lo  = wo_hi + M1;
        __nv_bfloat16* w1_hi  = wo_hi + 2*M1;         __nv_bfloat16* w1_lo  = w1_hi + M4;
        __nv_bfloat16* w2_hi  = w1_hi + 2*M4;         __nv_bfloat16* w2_lo  = w2_hi + M4;

        ln_split_kernel<<<NROWS/2, 256>>>(x, ln1g + l*DMODEL, ln1b + l*DMODEL, hhi, hlo);
        gemm_tc_kernel<false,false,false,true><<<gQKV, 256, GEMM_SMEM>>>(
            hhi, hlo, qkv_hi, qkv_lo, nullptr, nullptr, nullptr, qkvhi, qkvlo, NQKV, DMODEL);

        attn_tc_kernel<<<dim3(TLEN/64, NHEAD, BATCH), 128, ATT_SMEM>>>(
            qkvhi, qkvlo, qkvhi + 1024, qkvlo + 1024, qkvhi + 2048, qkvlo + 2048,
            athi, atlo, NQKV);

        gemm_tc_kernel<true,false,true,false><<<gD, 256, GEMM_SMEM>>>(
            athi, atlo, wo_hi, wo_lo, bo + l*DMODEL, x, x, nullptr, nullptr, DMODEL, DMODEL);

        ln_split_kernel<<<NROWS/2, 256>>>(x, ln2g + l*DMODEL, ln2b + l*DMODEL, hhi, hlo);
        gemm_tc_kernel<true,true,false,true><<<gF, 256, GEMM_SMEM>>>(
            hhi, hlo, w1_hi, w1_lo, b1 + (size_t)l*DFF, nullptr, nullptr, ffhi, fflo, DFF, DMODEL);

        gemm_tc_kernel<true,false,true,false><<<gD, 256, GEMM_SMEM>>>(
            ffhi, fflo, w2_hi, w2_lo, b2 + l*DMODEL, x, x, nullptr, nullptr, DMODEL, DFF);
    }

    ln_split_kernel<<<NROWS/2, 256>>>(x, lnfg, lnfb, hhi, hlo);
    gemm_tc_kernel<true,false,false,false><<<gV, 256, GEMM_SMEM>>>(
        hhi, hlo, wh_hi, wh_lo, bh, nullptr, out, nullptr, nullptr, VOCAB, DMODEL);
}